// round 3
// baseline (speedup 1.0000x reference)
#include <cuda_runtime.h>

#define B_ 8
#define C_ 32
#define F_ 32
#define Q_ 9
#define H_ 32
#define W_ 32

typedef unsigned long long u64;

__device__ __forceinline__ u64 pack2(float lo, float hi) {
    u64 r; asm("mov.b64 %0, {%1, %2};" : "=l"(r) : "f"(lo), "f"(hi)); return r;
}
__device__ __forceinline__ void unpack2(u64 v, float& lo, float& hi) {
    asm("mov.b64 {%0, %1}, %2;" : "=f"(lo), "=f"(hi) : "l"(v));
}
__device__ __forceinline__ u64 fma2(u64 a, u64 b, u64 c) {
    u64 d; asm("fma.rn.f32x2 %0, %1, %2, %3;" : "=l"(d) : "l"(a), "l"(b), "l"(c)); return d;
}
__device__ __forceinline__ u64 mul2(u64 a, u64 b) {
    u64 d; asm("mul.rn.f32x2 %0, %1, %2;" : "=l"(d) : "l"(a), "l"(b)); return d;
}
__device__ __forceinline__ u64 add2(u64 a, u64 b) {
    u64 d; asm("add.rn.f32x2 %0, %1, %2;" : "=l"(d) : "l"(a), "l"(b)); return d;
}
__device__ __forceinline__ float rcpf(float x) {
    float r; asm("rcp.approx.ftz.f32 %0, %1;" : "=f"(r) : "f"(x)); return r;
}

// smem: dup coeffs 9*32*10 u64 = 23040B + 2 plane buffers 2*18*34*4 = 4896B -> ~28KB
__global__ __launch_bounds__(128) void kaconv_kernel(
    const float* __restrict__ x,
    const float* __restrict__ nums,
    const float* __restrict__ denoms,
    float* __restrict__ out)
{
    __shared__ u64   cs2[Q_ * C_ * 10];
    __shared__ float splane[2][18 * 34];

    const int tid  = threadIdx.x;
    const int blk  = blockIdx.x;
    const int half = blk & 1;             // 16-row slab
    const int bf   = blk >> 1;
    const int f    = bf & (F_ - 1);
    const int b    = bf >> 5;
    const int row0 = half * 16;

    // ---- stage duplicated coefficients for this f (vectorized gmem loads) ----
    for (int e = tid; e < Q_ * C_; e += 128) {
        const int g = f * Q_ * C_ + e;
        const float2* np2 = (const float2*)(nums + g * 6);
        const float2 n0 = __ldg(np2);
        const float2 n1 = __ldg(np2 + 1);
        const float2 n2 = __ldg(np2 + 2);
        const float4 d4 = __ldg((const float4*)(denoms + g * 4));
        u64* o = cs2 + e * 10;
        o[0] = pack2(n0.x, n0.x); o[1] = pack2(n0.y, n0.y);
        o[2] = pack2(n1.x, n1.x); o[3] = pack2(n1.y, n1.y);
        o[4] = pack2(n2.x, n2.x); o[5] = pack2(n2.y, n2.y);
        o[6] = pack2(d4.x, d4.x); o[7] = pack2(d4.y, d4.y);
        o[8] = pack2(d4.z, d4.z); o[9] = pack2(d4.w, d4.w);
    }

    const float* xb = x + (size_t)(b * C_) * (H_ * W_);

    // stage zero-padded plane rows [row0-1 .. row0+16], cols [-1..32]
    auto stage = [&](int c, int buf) {
        const float* xc = xb + c * (H_ * W_);
        for (int i = tid; i < 18 * 34; i += 128) {
            const int r  = i / 34;
            const int cc = i - r * 34;
            const int gr = row0 - 1 + r;
            const int gc = cc - 1;
            float v = 0.f;
            if ((unsigned)gr < H_ && (unsigned)gc < W_)
                v = xc[gr * W_ + gc];
            splane[buf][i] = v;
        }
    };
    stage(0, 0);

    const int lane_r = tid >> 5;   // 0..3
    const int col    = tid & 31;   // conflict-free LDS column

    const u64 ONE2  = 0x3F8000003F800000ULL;   // {1.0f, 1.0f}
    const u64 AMASK = 0x7FFFFFFF7FFFFFFFULL;

    u64 acc0 = 0ULL, acc1 = 0ULL;

    for (int c = 0; c < C_; ++c) {
        __syncthreads();                         // buf[c&1] staged; prev compute done
        if (c + 1 < C_) stage(c + 1, (c + 1) & 1);
        const float* pl = splane[c & 1];

        #pragma unroll
        for (int q = 0; q < Q_; ++q) {
            const int dy = q / 3;
            const int dx = q - dy * 3;
            const ulonglong2* cp = (const ulonglong2*)(cs2 + (q * C_ + c) * 10);
            const ulonglong2 p01 = cp[0];   // {a0},{a1}
            const ulonglong2 p23 = cp[1];   // {a2},{a3}
            const ulonglong2 p45 = cp[2];   // {a4},{a5}
            const ulonglong2 d12 = cp[3];   // {b1},{b2}
            const ulonglong2 d34 = cp[4];   // {b3},{b4}

            const int base = (lane_r + dy) * 34 + col + dx;
            const u64 w0 = pack2(pl[base],           pl[base + 4 * 34]);
            const u64 w1 = pack2(pl[base + 8 * 34],  pl[base + 12 * 34]);

            // ---- vector 0: rows (lane_r, lane_r+4) ----
            u64 n0 = fma2(p45.y, w0, p45.x);
            n0 = fma2(n0, w0, p23.y);
            n0 = fma2(n0, w0, p23.x);
            n0 = fma2(n0, w0, p01.y);
            n0 = fma2(n0, w0, p01.x);
            u64 e0 = fma2(d34.y, w0, d34.x);
            e0 = fma2(e0, w0, d12.y);
            e0 = fma2(e0, w0, d12.x);
            e0 = mul2(e0, w0);
            e0 &= AMASK;
            e0 = add2(ONE2, e0);
            float el0, eh0; unpack2(e0, el0, eh0);
            const u64 r0 = pack2(rcpf(el0), rcpf(eh0));
            acc0 = fma2(n0, r0, acc0);

            // ---- vector 1: rows (lane_r+8, lane_r+12) ----
            u64 n1 = fma2(p45.y, w1, p45.x);
            n1 = fma2(n1, w1, p23.y);
            n1 = fma2(n1, w1, p23.x);
            n1 = fma2(n1, w1, p01.y);
            n1 = fma2(n1, w1, p01.x);
            u64 e1 = fma2(d34.y, w1, d34.x);
            e1 = fma2(e1, w1, d12.y);
            e1 = fma2(e1, w1, d12.x);
            e1 = mul2(e1, w1);
            e1 &= AMASK;
            e1 = add2(ONE2, e1);
            float el1, eh1; unpack2(e1, el1, eh1);
            const u64 r1 = pack2(rcpf(el1), rcpf(eh1));
            acc1 = fma2(n1, r1, acc1);
        }
    }

    // ---- write 4 pixels ----
    float o0, o1, o2, o3;
    unpack2(acc0, o0, o1);
    unpack2(acc1, o2, o3);
    float* ob = out + ((size_t)(b * F_ + f)) * (H_ * W_);
    ob[(row0 + lane_r)      * W_ + col] = o0;
    ob[(row0 + lane_r + 4)  * W_ + col] = o1;
    ob[(row0 + lane_r + 8)  * W_ + col] = o2;
    ob[(row0 + lane_r + 12) * W_ + col] = o3;
}

extern "C" void kernel_launch(void* const* d_in, const int* in_sizes, int n_in,
                              void* d_out, int out_size)
{
    const float* x      = (const float*)d_in[0];
    const float* nums   = (const float*)d_in[1];
    const float* denoms = (const float*)d_in[2];
    float* out          = (float*)d_out;
    (void)in_sizes; (void)n_in; (void)out_size;

    kaconv_kernel<<<B_ * F_ * 2, 128>>>(x, nums, denoms, out);
}

// round 4
// speedup vs baseline: 1.0584x; 1.0584x over previous
#include <cuda_runtime.h>

#define B_ 8
#define C_ 32
#define F_ 32
#define Q_ 9
#define H_ 32
#define W_ 32

#define PROWS 18            // 16-row slab + halo
#define PSTR  36            // padded col stride (cols -1..32 stored at 0..33)
#define PLANEF (PROWS * PSTR)   // 648 floats / plane

typedef unsigned long long u64;

__device__ __forceinline__ u64 pack2(float lo, float hi) {
    u64 r; asm("mov.b64 %0, {%1, %2};" : "=l"(r) : "f"(lo), "f"(hi)); return r;
}
__device__ __forceinline__ void unpack2(u64 v, float& lo, float& hi) {
    asm("mov.b64 {%0, %1}, %2;" : "=f"(lo), "=f"(hi) : "l"(v));
}
__device__ __forceinline__ u64 fma2(u64 a, u64 b, u64 c) {
    u64 d; asm("fma.rn.f32x2 %0, %1, %2, %3;" : "=l"(d) : "l"(a), "l"(b), "l"(c)); return d;
}
__device__ __forceinline__ u64 mul2(u64 a, u64 b) {
    u64 d; asm("mul.rn.f32x2 %0, %1, %2;" : "=l"(d) : "l"(a), "l"(b)); return d;
}
__device__ __forceinline__ u64 add2(u64 a, u64 b) {
    u64 d; asm("add.rn.f32x2 %0, %1, %2;" : "=l"(d) : "l"(a), "l"(b)); return d;
}
__device__ __forceinline__ float rcpf(float x) {
    float r; asm("rcp.approx.ftz.f32 %0, %1;" : "=f"(r) : "f"(x)); return r;
}

// smem: 2 buffers x 8 planes x 648 floats = 41472 B, aliased with the
// 8x256 u64 (16 KB) cross-warp reduction buffer.
__global__ __launch_bounds__(256, 4) void kaconv_kernel(
    const float* __restrict__ x,
    const float* __restrict__ nums,
    const float* __restrict__ denoms,
    float* __restrict__ out)
{
    __shared__ __align__(16) char smraw[2 * 8 * PLANEF * 4];
    float* planes = (float*)smraw;
    u64*   part   = (u64*)smraw;

    const int tid  = threadIdx.x;
    const int blk  = blockIdx.x;
    const int half = blk & 1;              // 16-row slab
    const int bf   = blk >> 1;
    const int f    = bf & (F_ - 1);
    const int b    = bf >> 5;
    const int row0 = half * 16;

    const int warp = tid >> 5;             // 0..7  -> channel owner
    const int lane = tid & 31;             // column

    const float* xb = x + (size_t)(b * C_) * (H_ * W_);

    // ---- cooperative staging of 8 channel planes (rounds of 8 channels) ----
    auto stage = [&](int r, int buf) {
        const int c0 = r * 8;
        float* dst = planes + buf * (8 * PLANEF);
        // 8 planes x 18 rows x 34 cols = 4896 elements
        for (int i = tid; i < 8 * PROWS * 34; i += 256) {
            const int ch  = i / (PROWS * 34);
            const int rem = i - ch * (PROWS * 34);
            const int rr  = rem / 34;
            const int cc  = rem - rr * 34;
            const int gr  = row0 - 1 + rr;
            const int gc  = cc - 1;
            float v = 0.f;
            if ((unsigned)gr < H_ && (unsigned)gc < W_)
                v = xb[(c0 + ch) * (H_ * W_) + gr * W_ + gc];
            dst[ch * PLANEF + rr * PSTR + cc] = v;
        }
    };
    stage(0, 0);

    const u64 ONE2  = 0x3F8000003F800000ULL;
    const u64 AMASK = 0x7FFFFFFF7FFFFFFFULL;

    u64 acc[8];
    #pragma unroll
    for (int j = 0; j < 8; ++j) acc[j] = 0ULL;

    for (int r = 0; r < 4; ++r) {
        __syncthreads();                       // buf[r&1] staged; buf[r^1] free
        if (r + 1 < 4) stage(r + 1, (r + 1) & 1);

        const int c = r * 8 + warp;
        const float* pl = planes + (r & 1) * (8 * PLANEF) + warp * PLANEF + lane;

        #pragma unroll
        for (int q = 0; q < Q_; ++q) {
            const int dy = q / 3;
            const int dx = q - dy * 3;
            // warp-uniform coefficient loads, L2-hot
            const int g = (f * Q_ + q) * C_ + c;
            const float2* np = (const float2*)(nums + (size_t)g * 6);
            const float2 n01 = __ldg(np);
            const float2 n23 = __ldg(np + 1);
            const float2 n45 = __ldg(np + 2);
            const float4 dd  = __ldg((const float4*)(denoms + (size_t)g * 4));
            const u64 a0 = pack2(n01.x, n01.x), a1 = pack2(n01.y, n01.y);
            const u64 a2 = pack2(n23.x, n23.x), a3 = pack2(n23.y, n23.y);
            const u64 a4 = pack2(n45.x, n45.x), a5 = pack2(n45.y, n45.y);
            const u64 b1 = pack2(dd.x, dd.x),   b2 = pack2(dd.y, dd.y);
            const u64 b3 = pack2(dd.z, dd.z),   b4 = pack2(dd.w, dd.w);

            const float* pw = pl + dy * PSTR + dx;
            #pragma unroll
            for (int j = 0; j < 8; ++j) {
                const float w_lo = pw[(2 * j)     * PSTR];
                const float w_hi = pw[(2 * j + 1) * PSTR];
                const u64 w2 = pack2(w_lo, w_hi);

                u64 num = fma2(a5, w2, a4);
                num = fma2(num, w2, a3);
                num = fma2(num, w2, a2);
                num = fma2(num, w2, a1);
                num = fma2(num, w2, a0);

                u64 den = fma2(b4, w2, b3);
                den = fma2(den, w2, b2);
                den = fma2(den, w2, b1);
                den = mul2(den, w2);
                den &= AMASK;
                den = add2(ONE2, den);

                float dl, dh; unpack2(den, dl, dh);
                const u64 rr2 = pack2(rcpf(dl), rcpf(dh));
                acc[j] = fma2(num, rr2, acc[j]);
            }
        }
    }

    // ---- deterministic cross-warp reduction (8 channel-partials per pixel) ----
    __syncthreads();                           // all plane reads done; alias smem
    #pragma unroll
    for (int j = 0; j < 8; ++j)
        part[warp * 256 + j * 32 + lane] = acc[j];
    __syncthreads();

    {
        const int j  = tid >> 5;               // row pair 0..7
        const int xx = tid & 31;               // column
        u64 s = part[j * 32 + xx];
        #pragma unroll
        for (int w = 1; w < 8; ++w)
            s = add2(s, part[w * 256 + j * 32 + xx]);
        float lo, hi; unpack2(s, lo, hi);
        float* ob = out + ((size_t)(b * F_ + f)) * (H_ * W_);
        ob[(row0 + 2 * j)     * W_ + xx] = lo;
        ob[(row0 + 2 * j + 1) * W_ + xx] = hi;
    }
}

extern "C" void kernel_launch(void* const* d_in, const int* in_sizes, int n_in,
                              void* d_out, int out_size)
{
    const float* x      = (const float*)d_in[0];
    const float* nums   = (const float*)d_in[1];
    const float* denoms = (const float*)d_in[2];
    float* out          = (float*)d_out;
    (void)in_sizes; (void)n_in; (void)out_size;

    kaconv_kernel<<<B_ * F_ * 2, 256>>>(x, nums, denoms, out);
}